// round 8
// baseline (speedup 1.0000x reference)
#include <cuda_runtime.h>
#include <cuda_bf16.h>

// GeometricHyperConnections — fused, HBM-bound.
// b=4, s=4, T=2048, d=2048, k=4.
// One CTA per (b,t) token; 512 threads; ONE block barrier.
// SINGLE PASS: each thread owns one float4 column, keeps the 4 stream values
// in registers across the barrier (no SMEM staging, no re-read). All r/bo
// traffic is streaming (__ldcs/__stcs). Every warp redundantly computes the
// 4x4 Sinkhorn in lanes 0-15.

#define T_DIM 2048
#define D_DIM 2048
#define D4    512         // D_DIM/4
#define B_DIM 4
#define S_DIM 4
#define K_DIM 4
#define NWARP 16
#define TAU   0.05f
#define LOGM  (-1.3862943611198906f)   // -log(4)
#define RMSEPS 1e-6f

__global__ void __launch_bounds__(512, 2)
ghc_kernel(const float* __restrict__ resid,
           const float* __restrict__ branch,
           const float* __restrict__ rmsw,
           const float* __restrict__ projW,
           const float* __restrict__ log_sigma,
           const float* __restrict__ pre_logits,
           const float* __restrict__ post_logits,
           float* __restrict__ out_bi,     // (B,T,D)
           float* __restrict__ out_mix)    // (B*S,T,D)
{
    __shared__ float red[NWARP][20];        // per-warp partials
    __shared__ float coords_w[NWARP][16];   // per-warp private scratch
    __shared__ float Hs_w[NWARP][16];       // per-warp H result

    const int tid  = threadIdx.x;
    const int warp = tid >> 5, lane = tid & 31;
    const int m    = blockIdx.x;
    const int bi   = m >> 11;               // m / T_DIM
    const int t    = m & (T_DIM - 1);

    const float4* R4  = (const float4*)resid;
    const float4* W4  = (const float4*)rmsw;
    const float4* P4  = (const float4*)projW;
    const float4* BO4 = (const float4*)branch;

    unsigned rbase[S_DIM];
#pragma unroll
    for (int si = 0; si < S_DIM; si++)
        rbase[si] = (unsigned)((bi * S_DIM + si) * T_DIM + t) * D4;
    const unsigned bbase = (unsigned)(bi * T_DIM + t) * D4;

    // ---- Hpre / Hpost: every thread computes both tiny softmaxes ----------
    float hp[4], hq[4];
    {
        float l[4], mx, sm;
#pragma unroll
        for (int i = 0; i < 4; i++) l[i] = __ldg(&pre_logits[i]);
        mx = fmaxf(fmaxf(l[0], l[1]), fmaxf(l[2], l[3]));
        sm = 0.f;
#pragma unroll
        for (int i = 0; i < 4; i++) { hp[i] = __expf(l[i] - mx); sm += hp[i]; }
        sm = 1.f / sm;
#pragma unroll
        for (int i = 0; i < 4; i++) hp[i] *= sm;
#pragma unroll
        for (int i = 0; i < 4; i++) l[i] = __ldg(&post_logits[i]);
        mx = fmaxf(fmaxf(l[0], l[1]), fmaxf(l[2], l[3]));
        sm = 0.f;
#pragma unroll
        for (int i = 0; i < 4; i++) { hq[i] = __expf(l[i] - mx); sm += hq[i]; }
        sm = 1.f / sm;
#pragma unroll
        for (int i = 0; i < 4; i++) hq[i] *= sm;
    }

    float4* OBI = (float4*)out_bi;
    float4* OMX = (float4*)out_mix;

    // ---------------- Single pass: load r (kept in regs) + stats -----------
    const int c = tid;                      // one float4 column per thread
    float4 r[S_DIM];
#pragma unroll
    for (int s = 0; s < S_DIM; s++) r[s] = __ldcs(&R4[rbase[s] + c]);
    const float4 bo = __ldcs(&BO4[bbase + c]);

    // branch_input: store immediately (hp known up front)
    {
        float4 o;
        o.x = hp[0]*r[0].x + hp[1]*r[1].x + hp[2]*r[2].x + hp[3]*r[3].x;
        o.y = hp[0]*r[0].y + hp[1]*r[1].y + hp[2]*r[2].y + hp[3]*r[3].y;
        o.z = hp[0]*r[0].z + hp[1]*r[1].z + hp[2]*r[2].z + hp[3]*r[3].z;
        o.w = hp[0]*r[0].w + hp[1]*r[1].w + hp[2]*r[2].w + hp[3]*r[3].w;
        __stcs(&OBI[bbase + c], o);
    }

    // acc[0..3] = sumsq[s]; acc[4 + s*4 + k] = dot[s][k]
    float acc[20];
    {
        const float4 w  = W4[c];
        const float4 p0 = P4[0 * D4 + c];
        const float4 p1 = P4[1 * D4 + c];
        const float4 p2 = P4[2 * D4 + c];
        const float4 p3 = P4[3 * D4 + c];
#pragma unroll
        for (int s = 0; s < S_DIM; s++) {
            acc[s] = r[s].x*r[s].x + r[s].y*r[s].y + r[s].z*r[s].z + r[s].w*r[s].w;
            const float ax = r[s].x*w.x, ay = r[s].y*w.y,
                        az = r[s].z*w.z, aw = r[s].w*w.w;
            acc[4 + s*4 + 0] = ax*p0.x + ay*p0.y + az*p0.z + aw*p0.w;
            acc[4 + s*4 + 1] = ax*p1.x + ay*p1.y + az*p1.z + aw*p1.w;
            acc[4 + s*4 + 2] = ax*p2.x + ay*p2.y + az*p2.z + aw*p2.w;
            acc[4 + s*4 + 3] = ax*p3.x + ay*p3.y + az*p3.z + aw*p3.w;
        }
    }

#pragma unroll
    for (int v = 0; v < 20; v++) {
        float x = acc[v];
#pragma unroll
        for (int off = 16; off; off >>= 1)
            x += __shfl_xor_sync(0xffffffffu, x, off);
        acc[v] = x;
    }
    if (lane == 0) {
#pragma unroll
        for (int v = 0; v < 20; v++) red[warp][v] = acc[v];
    }

    __syncthreads();   // the ONLY block barrier

    // ---- Every warp: coords + Sinkhorn (lanes 0-15), fully parallel -------
    if (lane < 16) {
        const int si = lane >> 2;
        float ssq = 0.f, dsum = 0.f;
#pragma unroll
        for (int w = 0; w < NWARP; w++) {
            ssq  += red[w][si];
            dsum += red[w][4 + lane];
        }
        const float scale = rsqrtf(ssq * (1.f / (float)D_DIM) + RMSEPS);
        coords_w[warp][lane] = scale * dsum;
    }
    __syncwarp();
    if (lane < 16) {
        const int i = lane >> 2, jj = lane & 3;
        float ds = 0.f;
#pragma unroll
        for (int k = 0; k < K_DIM; k++) {
            const float df = coords_w[warp][i * 4 + k] - coords_w[warp][jj * 4 + k];
            ds += df * df;
        }
        const float sigma_sq = __expf(2.f * __ldg(log_sigma));
        const float Z = -ds / (2.f * sigma_sq * TAU);

        float u = 0.f, v = 0.f;
        const unsigned M = 0x0000ffffu;
#pragma unroll
        for (int it = 0; it < 10; it++) {
            float t0 = Z + v;
            float mx = t0;
            mx = fmaxf(mx, __shfl_xor_sync(M, mx, 1));
            mx = fmaxf(mx, __shfl_xor_sync(M, mx, 2));
            float p = __expf(t0 - mx);
            p += __shfl_xor_sync(M, p, 1);
            p += __shfl_xor_sync(M, p, 2);
            u = LOGM - (mx + __logf(p));
            float t1 = Z + u;
            mx = t1;
            mx = fmaxf(mx, __shfl_xor_sync(M, mx, 4));
            mx = fmaxf(mx, __shfl_xor_sync(M, mx, 8));
            p = __expf(t1 - mx);
            p += __shfl_xor_sync(M, p, 4);
            p += __shfl_xor_sync(M, p, 8);
            v = LOGM - (mx + __logf(p));
        }
        Hs_w[warp][lane] = __expf(Z + u + v) * (float)S_DIM;
    }
    __syncwarp();

    // ---------------- Mixed outputs straight from registers ----------------
    const float* H = Hs_w[warp];
#pragma unroll
    for (int u = 0; u < 4; u++) {
        const float h0 = H[0 * 4 + u], h1 = H[1 * 4 + u],
                    h2 = H[2 * 4 + u], h3 = H[3 * 4 + u], hb = hq[u];
        float4 q;
        q.x = hb*bo.x + h0*r[0].x + h1*r[1].x + h2*r[2].x + h3*r[3].x;
        q.y = hb*bo.y + h0*r[0].y + h1*r[1].y + h2*r[2].y + h3*r[3].y;
        q.z = hb*bo.z + h0*r[0].z + h1*r[1].z + h2*r[2].z + h3*r[3].z;
        q.w = hb*bo.w + h0*r[0].w + h1*r[1].w + h2*r[2].w + h3*r[3].w;
        __stcs(&OMX[rbase[u] + c], q);
    }
}

extern "C" void kernel_launch(void* const* d_in, const int* in_sizes, int n_in,
                              void* d_out, int out_size)
{
    const float* resid       = (const float*)d_in[0];
    const float* branch      = (const float*)d_in[1];
    const float* rmsw        = (const float*)d_in[2];
    const float* projW       = (const float*)d_in[3];
    const float* log_sigma   = (const float*)d_in[4];
    const float* pre_logits  = (const float*)d_in[5];
    const float* post_logits = (const float*)d_in[6];

    float* out_bi  = (float*)d_out;                                   // (B,T,D) first
    float* out_mix = (float*)d_out + (size_t)B_DIM * T_DIM * D_DIM;   // then (B*S,T,D)

    dim3 grid(B_DIM * T_DIM);
    dim3 block(512);
    ghc_kernel<<<grid, block>>>(resid, branch, rmsw, projW, log_sigma,
                                pre_logits, post_logits, out_bi, out_mix);
}

// round 10
// speedup vs baseline: 1.1268x; 1.1268x over previous
#include <cuda_runtime.h>
#include <cuda_bf16.h>

// GeometricHyperConnections — fused, HBM-bound.
// b=4, s=4, T=2048, d=2048, k=4.
// One CTA per 4 consecutive tokens; 512 threads (one float4 column each).
// r is register-resident per token (no staging, no re-read). Fused w*proj
// table staged once in SMEM. Sinkhorn computed by warp 0 ONLY (8192 total
// executions); other warps prefetch the next token's r during it.

#define T_DIM 2048
#define D_DIM 2048
#define D4    512         // D_DIM/4
#define B_DIM 4
#define S_DIM 4
#define K_DIM 4
#define TPC   4           // tokens per CTA
#define NWARP 16
#define TAU   0.05f
#define LOGM  (-1.3862943611198906f)   // -log(4)
#define RMSEPS 1e-6f

__global__ void __launch_bounds__(512, 2)
ghc_kernel(const float* __restrict__ resid,
           const float* __restrict__ branch,
           const float* __restrict__ rmsw,
           const float* __restrict__ projW,
           const float* __restrict__ log_sigma,
           const float* __restrict__ pre_logits,
           const float* __restrict__ post_logits,
           float* __restrict__ out_bi,     // (B,T,D)
           float* __restrict__ out_mix)    // (B*S,T,D)
{
    __shared__ float4 wp4[K_DIM][D4];      // fused w*proj table (32 KB)
    __shared__ float  red[NWARP][20];      // per-warp partials
    __shared__ float  coords[16];          // warp-0 scratch
    __shared__ float  Hs[16];              // H for current token

    const int tid  = threadIdx.x;
    const int warp = tid >> 5, lane = tid & 31;
    const int blk  = blockIdx.x;
    const int bi   = blk >> 9;             // blk / (T_DIM/TPC)
    const int t0   = (blk & 511) * TPC;

    const float4* R4  = (const float4*)resid;
    const float4* W4  = (const float4*)rmsw;
    const float4* P4  = (const float4*)projW;
    const float4* BO4 = (const float4*)branch;
    float4* OBI = (float4*)out_bi;
    float4* OMX = (float4*)out_mix;

    // ---- fill fused weight table (once per CTA) ---------------------------
    {
        const float4 w = W4[tid];
#pragma unroll
        for (int k = 0; k < K_DIM; k++) {
            const float4 p = P4[k * D4 + tid];
            wp4[k][tid] = make_float4(w.x * p.x, w.y * p.y, w.z * p.z, w.w * p.w);
        }
    }

    // ---- Hpre / Hpost (per-thread, tiny) ----------------------------------
    float hp[4], hq[4];
    {
        float l[4], mx, sm;
#pragma unroll
        for (int i = 0; i < 4; i++) l[i] = __ldg(&pre_logits[i]);
        mx = fmaxf(fmaxf(l[0], l[1]), fmaxf(l[2], l[3]));
        sm = 0.f;
#pragma unroll
        for (int i = 0; i < 4; i++) { hp[i] = __expf(l[i] - mx); sm += hp[i]; }
        sm = 1.f / sm;
#pragma unroll
        for (int i = 0; i < 4; i++) hp[i] *= sm;
#pragma unroll
        for (int i = 0; i < 4; i++) l[i] = __ldg(&post_logits[i]);
        mx = fmaxf(fmaxf(l[0], l[1]), fmaxf(l[2], l[3]));
        sm = 0.f;
#pragma unroll
        for (int i = 0; i < 4; i++) { hq[i] = __expf(l[i] - mx); sm += hq[i]; }
        sm = 1.f / sm;
#pragma unroll
        for (int i = 0; i < 4; i++) hq[i] *= sm;
    }

    // ---- addresses (float4 units) + first token's loads -------------------
    unsigned rb[S_DIM];
#pragma unroll
    for (int s = 0; s < S_DIM; s++)
        rb[s] = (unsigned)((bi * S_DIM + s) * T_DIM + t0) * D4 + tid;
    unsigned bb = (unsigned)(bi * T_DIM + t0) * D4 + tid;

    float4 rc[S_DIM];
#pragma unroll
    for (int s = 0; s < S_DIM; s++) rc[s] = __ldcs(&R4[rb[s]]);
    float4 bo = __ldcs(&BO4[bb]);

    __syncthreads();   // wp table ready

    // =================== token loop =======================================
#pragma unroll
    for (int i = 0; i < TPC; i++) {
        // -- branch_input (needs only hp): store immediately
        {
            float4 o;
            o.x = hp[0]*rc[0].x + hp[1]*rc[1].x + hp[2]*rc[2].x + hp[3]*rc[3].x;
            o.y = hp[0]*rc[0].y + hp[1]*rc[1].y + hp[2]*rc[2].y + hp[3]*rc[3].y;
            o.z = hp[0]*rc[0].z + hp[1]*rc[1].z + hp[2]*rc[2].z + hp[3]*rc[3].z;
            o.w = hp[0]*rc[0].w + hp[1]*rc[1].w + hp[2]*rc[2].w + hp[3]*rc[3].w;
            __stcs(&OBI[bb], o);
        }

        // -- stats: acc[0..3]=sumsq, acc[4+s*4+k]=dot(r_s, w*p_k)
        float acc[20];
#pragma unroll
        for (int s = 0; s < S_DIM; s++)
            acc[s] = rc[s].x*rc[s].x + rc[s].y*rc[s].y
                   + rc[s].z*rc[s].z + rc[s].w*rc[s].w;
#pragma unroll
        for (int k = 0; k < K_DIM; k++) {
            const float4 wk = wp4[k][tid];
#pragma unroll
            for (int s = 0; s < S_DIM; s++)
                acc[4 + s*4 + k] = rc[s].x*wk.x + rc[s].y*wk.y
                                 + rc[s].z*wk.z + rc[s].w*wk.w;
        }

        // -- warp reduction of 20 values
#pragma unroll
        for (int v = 0; v < 20; v++) {
            float x = acc[v];
#pragma unroll
            for (int off = 16; off; off >>= 1)
                x += __shfl_xor_sync(0xffffffffu, x, off);
            acc[v] = x;
        }
        if (lane == 0) {
#pragma unroll
            for (int v = 0; v < 20; v++) red[warp][v] = acc[v];
        }

        // -- prefetch next token BEFORE barrier (in flight during Sinkhorn)
        float4 rn[S_DIM], bon;
        if (i + 1 < TPC) {
#pragma unroll
            for (int s = 0; s < S_DIM; s++) rn[s] = __ldcs(&R4[rb[s] + D4]);
            bon = __ldcs(&BO4[bb + D4]);
        }

        __syncthreads();   // barrier 1: red complete

        // -- warp 0 ONLY: coords + Sinkhorn -> Hs
        if (warp == 0) {
            if (lane < 16) {
                const int si = lane >> 2;
                float ssq = 0.f, dsum = 0.f;
#pragma unroll
                for (int w = 0; w < NWARP; w++) {
                    ssq  += red[w][si];
                    dsum += red[w][4 + lane];
                }
                const float scale = rsqrtf(ssq * (1.f / (float)D_DIM) + RMSEPS);
                coords[lane] = scale * dsum;
            }
            __syncwarp();
            if (lane < 16) {
                const int ii = lane >> 2, jj = lane & 3;
                float ds = 0.f;
#pragma unroll
                for (int k = 0; k < K_DIM; k++) {
                    const float df = coords[ii * 4 + k] - coords[jj * 4 + k];
                    ds += df * df;
                }
                const float sigma_sq = __expf(2.f * __ldg(log_sigma));
                const float Z = -ds / (2.f * sigma_sq * TAU);

                float u = 0.f, v = 0.f;
                const unsigned M = 0x0000ffffu;
#pragma unroll
                for (int it = 0; it < 10; it++) {
                    float tt = Z + v;
                    float mx = tt;
                    mx = fmaxf(mx, __shfl_xor_sync(M, mx, 1));
                    mx = fmaxf(mx, __shfl_xor_sync(M, mx, 2));
                    float p = __expf(tt - mx);
                    p += __shfl_xor_sync(M, p, 1);
                    p += __shfl_xor_sync(M, p, 2);
                    u = LOGM - (mx + __logf(p));
                    tt = Z + u;
                    mx = tt;
                    mx = fmaxf(mx, __shfl_xor_sync(M, mx, 4));
                    mx = fmaxf(mx, __shfl_xor_sync(M, mx, 8));
                    p = __expf(tt - mx);
                    p += __shfl_xor_sync(M, p, 4);
                    p += __shfl_xor_sync(M, p, 8);
                    v = LOGM - (mx + __logf(p));
                }
                Hs[lane] = __expf(Z + u + v) * (float)S_DIM;
            }
        }

        __syncthreads();   // barrier 2: Hs ready

        // -- mixed outputs straight from registers
#pragma unroll
        for (int u = 0; u < 4; u++) {
            const float h0 = Hs[0*4 + u], h1 = Hs[1*4 + u],
                        h2 = Hs[2*4 + u], h3 = Hs[3*4 + u], hb = hq[u];
            float4 q;
            q.x = hb*bo.x + h0*rc[0].x + h1*rc[1].x + h2*rc[2].x + h3*rc[3].x;
            q.y = hb*bo.y + h0*rc[0].y + h1*rc[1].y + h2*rc[2].y + h3*rc[3].y;
            q.z = hb*bo.z + h0*rc[0].z + h1*rc[1].z + h2*rc[2].z + h3*rc[3].z;
            q.w = hb*bo.w + h0*rc[0].w + h1*rc[1].w + h2*rc[2].w + h3*rc[3].w;
            __stcs(&OMX[rb[u]], q);
        }

        // -- rotate to next token
        if (i + 1 < TPC) {
#pragma unroll
            for (int s = 0; s < S_DIM; s++) { rc[s] = rn[s]; rb[s] += D4; }
            bo = bon;
            bb += D4;
        }
    }
}

extern "C" void kernel_launch(void* const* d_in, const int* in_sizes, int n_in,
                              void* d_out, int out_size)
{
    const float* resid       = (const float*)d_in[0];
    const float* branch      = (const float*)d_in[1];
    const float* rmsw        = (const float*)d_in[2];
    const float* projW       = (const float*)d_in[3];
    const float* log_sigma   = (const float*)d_in[4];
    const float* pre_logits  = (const float*)d_in[5];
    const float* post_logits = (const float*)d_in[6];

    float* out_bi  = (float*)d_out;                                   // (B,T,D) first
    float* out_mix = (float*)d_out + (size_t)B_DIM * T_DIM * D_DIM;   // then (B*S,T,D)

    dim3 grid(B_DIM * T_DIM / TPC);   // 2048 CTAs x 4 tokens
    dim3 block(512);
    ghc_kernel<<<grid, block>>>(resid, branch, rmsw, projW, log_sigma,
                                pre_logits, post_logits, out_bi, out_mix);
}

// round 11
// speedup vs baseline: 1.2451x; 1.1050x over previous
#include <cuda_runtime.h>
#include <cuda_bf16.h>

// GeometricHyperConnections — fused, HBM-bound.
// b=4, s=4, T=2048, d=2048, k=4.
// One CTA per 4 consecutive tokens; 512 threads (one float4 column each).
// r register-resident per token. Fused w*proj table in SMEM.
// Sinkhorn: SCALAR multiplicative form in lane 0 of warp 0 (~900 cyc, no
// shuffles; safe without max-subtraction since K diagonal = 1).
// The next token's branch_input is computed inside the Sinkhorn window.

#define T_DIM 2048
#define D_DIM 2048
#define D4    512         // D_DIM/4
#define B_DIM 4
#define S_DIM 4
#define K_DIM 4
#define TPC   4           // tokens per CTA
#define NWARP 16
#define TAU   0.05f
#define RMSEPS 1e-6f

__global__ void __launch_bounds__(512, 2)
ghc_kernel(const float* __restrict__ resid,
           const float* __restrict__ branch,
           const float* __restrict__ rmsw,
           const float* __restrict__ projW,
           const float* __restrict__ log_sigma,
           const float* __restrict__ pre_logits,
           const float* __restrict__ post_logits,
           float* __restrict__ out_bi,     // (B,T,D)
           float* __restrict__ out_mix)    // (B*S,T,D)
{
    __shared__ float4 wp4[K_DIM][D4];      // fused w*proj table (32 KB)
    __shared__ float  red[NWARP][20];      // per-warp partials
    __shared__ float  coords[16];          // warp-0 scratch
    __shared__ float  Hs[16];              // H for current token

    const int tid  = threadIdx.x;
    const int warp = tid >> 5, lane = tid & 31;
    const int blk  = blockIdx.x;
    const int bi   = blk >> 9;             // blk / (T_DIM/TPC)
    const int t0   = (blk & 511) * TPC;

    const float4* R4  = (const float4*)resid;
    const float4* W4  = (const float4*)rmsw;
    const float4* P4  = (const float4*)projW;
    const float4* BO4 = (const float4*)branch;
    float4* OBI = (float4*)out_bi;
    float4* OMX = (float4*)out_mix;

    // ---- fill fused weight table (once per CTA) ---------------------------
    {
        const float4 w = W4[tid];
#pragma unroll
        for (int k = 0; k < K_DIM; k++) {
            const float4 p = P4[k * D4 + tid];
            wp4[k][tid] = make_float4(w.x * p.x, w.y * p.y, w.z * p.z, w.w * p.w);
        }
    }

    // ---- Hpre / Hpost (per-thread, tiny) ----------------------------------
    float hp[4], hq[4];
    {
        float l[4], mx, sm;
#pragma unroll
        for (int i = 0; i < 4; i++) l[i] = __ldg(&pre_logits[i]);
        mx = fmaxf(fmaxf(l[0], l[1]), fmaxf(l[2], l[3]));
        sm = 0.f;
#pragma unroll
        for (int i = 0; i < 4; i++) { hp[i] = __expf(l[i] - mx); sm += hp[i]; }
        sm = 1.f / sm;
#pragma unroll
        for (int i = 0; i < 4; i++) hp[i] *= sm;
#pragma unroll
        for (int i = 0; i < 4; i++) l[i] = __ldg(&post_logits[i]);
        mx = fmaxf(fmaxf(l[0], l[1]), fmaxf(l[2], l[3]));
        sm = 0.f;
#pragma unroll
        for (int i = 0; i < 4; i++) { hq[i] = __expf(l[i] - mx); sm += hq[i]; }
        sm = 1.f / sm;
#pragma unroll
        for (int i = 0; i < 4; i++) hq[i] *= sm;
    }

    // ---- addresses (float4 units) + first token's loads -------------------
    unsigned rb[S_DIM];
#pragma unroll
    for (int s = 0; s < S_DIM; s++)
        rb[s] = (unsigned)((bi * S_DIM + s) * T_DIM + t0) * D4 + tid;
    unsigned bb = (unsigned)(bi * T_DIM + t0) * D4 + tid;

    float4 rc[S_DIM];
#pragma unroll
    for (int s = 0; s < S_DIM; s++) rc[s] = __ldcs(&R4[rb[s]]);
    float4 bo = __ldcs(&BO4[bb]);

    // branch_input for token 0 (needs only hp)
    {
        float4 o;
        o.x = hp[0]*rc[0].x + hp[1]*rc[1].x + hp[2]*rc[2].x + hp[3]*rc[3].x;
        o.y = hp[0]*rc[0].y + hp[1]*rc[1].y + hp[2]*rc[2].y + hp[3]*rc[3].y;
        o.z = hp[0]*rc[0].z + hp[1]*rc[1].z + hp[2]*rc[2].z + hp[3]*rc[3].z;
        o.w = hp[0]*rc[0].w + hp[1]*rc[1].w + hp[2]*rc[2].w + hp[3]*rc[3].w;
        __stcs(&OBI[bb], o);
    }

    __syncthreads();   // wp table ready

    // =================== token loop =======================================
#pragma unroll
    for (int i = 0; i < TPC; i++) {
        // -- stats: acc[0..3]=sumsq, acc[4+s*4+k]=dot(r_s, w*p_k)
        float acc[20];
#pragma unroll
        for (int s = 0; s < S_DIM; s++)
            acc[s] = rc[s].x*rc[s].x + rc[s].y*rc[s].y
                   + rc[s].z*rc[s].z + rc[s].w*rc[s].w;
#pragma unroll
        for (int k = 0; k < K_DIM; k++) {
            const float4 wk = wp4[k][tid];
#pragma unroll
            for (int s = 0; s < S_DIM; s++)
                acc[4 + s*4 + k] = rc[s].x*wk.x + rc[s].y*wk.y
                                 + rc[s].z*wk.z + rc[s].w*wk.w;
        }

        // -- warp reduction of 20 values
#pragma unroll
        for (int v = 0; v < 20; v++) {
            float x = acc[v];
#pragma unroll
            for (int off = 16; off; off >>= 1)
                x += __shfl_xor_sync(0xffffffffu, x, off);
            acc[v] = x;
        }
        if (lane == 0) {
#pragma unroll
            for (int v = 0; v < 20; v++) red[warp][v] = acc[v];
        }

        // -- prefetch next token BEFORE barrier (in flight during Sinkhorn)
        float4 rn[S_DIM], bon;
        if (i + 1 < TPC) {
#pragma unroll
            for (int s = 0; s < S_DIM; s++) rn[s] = __ldcs(&R4[rb[s] + D4]);
            bon = __ldcs(&BO4[bb + D4]);
        }

        __syncthreads();   // barrier 1: red complete

        // -- warp 0: coords (lanes 0-15), then SCALAR Sinkhorn in lane 0
        if (warp == 0) {
            if (lane < 16) {
                const int si = lane >> 2;
                float ssq = 0.f, dsum = 0.f;
#pragma unroll
                for (int w = 0; w < NWARP; w++) {
                    ssq  += red[w][si];
                    dsum += red[w][4 + lane];
                }
                const float scale = rsqrtf(ssq * (1.f / (float)D_DIM) + RMSEPS);
                coords[lane] = scale * dsum;
            }
            __syncwarp();
            if (lane == 0) {
                // Z_ij = -dist_sq/(2*sigma^2*tau); K = exp(Z); diagonal = 1.
                const float inv = __expf(-2.f * __ldg(log_sigma)) * (0.5f / TAU);
                float C[16];
#pragma unroll
                for (int x = 0; x < 16; x++) C[x] = coords[x];
                float K[16];
#pragma unroll
                for (int ii = 0; ii < 4; ii++) {
#pragma unroll
                    for (int jj = 0; jj < 4; jj++) {
                        float ds = 0.f;
#pragma unroll
                        for (int k = 0; k < 4; k++) {
                            const float df = C[ii*4 + k] - C[jj*4 + k];
                            ds += df * df;
                        }
                        K[ii*4 + jj] = __expf(-ds * inv);
                    }
                }
                // multiplicative Sinkhorn: a = 1/4 / (K b); b = 1/4 / (K^T a)
                float a[4], b[4] = {1.f, 1.f, 1.f, 1.f};
#pragma unroll
                for (int it = 0; it < 10; it++) {
#pragma unroll
                    for (int ii = 0; ii < 4; ii++) {
                        const float d = K[ii*4+0]*b[0] + K[ii*4+1]*b[1]
                                      + K[ii*4+2]*b[2] + K[ii*4+3]*b[3];
                        a[ii] = __fdividef(0.25f, d);
                    }
#pragma unroll
                    for (int jj = 0; jj < 4; jj++) {
                        const float d = K[0*4+jj]*a[0] + K[1*4+jj]*a[1]
                                      + K[2*4+jj]*a[2] + K[3*4+jj]*a[3];
                        b[jj] = __fdividef(0.25f, d);
                    }
                }
#pragma unroll
                for (int ii = 0; ii < 4; ii++)
#pragma unroll
                    for (int jj = 0; jj < 4; jj++)
                        Hs[ii*4 + jj] = 4.f * K[ii*4 + jj] * a[ii] * b[jj];
            }
        }

        // -- meanwhile: branch_input for NEXT token (only needs hp + rn)
        if (i + 1 < TPC) {
            float4 o;
            o.x = hp[0]*rn[0].x + hp[1]*rn[1].x + hp[2]*rn[2].x + hp[3]*rn[3].x;
            o.y = hp[0]*rn[0].y + hp[1]*rn[1].y + hp[2]*rn[2].y + hp[3]*rn[3].y;
            o.z = hp[0]*rn[0].z + hp[1]*rn[1].z + hp[2]*rn[2].z + hp[3]*rn[3].z;
            o.w = hp[0]*rn[0].w + hp[1]*rn[1].w + hp[2]*rn[2].w + hp[3]*rn[3].w;
            __stcs(&OBI[bb + D4], o);
        }

        __syncthreads();   // barrier 2: Hs ready

        // -- mixed outputs straight from registers
#pragma unroll
        for (int u = 0; u < 4; u++) {
            const float h0 = Hs[0*4 + u], h1 = Hs[1*4 + u],
                        h2 = Hs[2*4 + u], h3 = Hs[3*4 + u], hb = hq[u];
            float4 q;
            q.x = hb*bo.x + h0*rc[0].x + h1*rc[1].x + h2*rc[2].x + h3*rc[3].x;
            q.y = hb*bo.y + h0*rc[0].y + h1*rc[1].y + h2*rc[2].y + h3*rc[3].y;
            q.z = hb*bo.z + h0*rc[0].z + h1*rc[1].z + h2*rc[2].z + h3*rc[3].z;
            q.w = hb*bo.w + h0*rc[0].w + h1*rc[1].w + h2*rc[2].w + h3*rc[3].w;
            __stcs(&OMX[rb[u]], q);
        }

        // -- rotate to next token
        if (i + 1 < TPC) {
#pragma unroll
            for (int s = 0; s < S_DIM; s++) { rc[s] = rn[s]; rb[s] += D4; }
            bo = bon;
            bb += D4;
        }
    }
}

extern "C" void kernel_launch(void* const* d_in, const int* in_sizes, int n_in,
                              void* d_out, int out_size)
{
    const float* resid       = (const float*)d_in[0];
    const float* branch      = (const float*)d_in[1];
    const float* rmsw        = (const float*)d_in[2];
    const float* projW       = (const float*)d_in[3];
    const float* log_sigma   = (const float*)d_in[4];
    const float* pre_logits  = (const float*)d_in[5];
    const float* post_logits = (const float*)d_in[6];

    float* out_bi  = (float*)d_out;                                   // (B,T,D) first
    float* out_mix = (float*)d_out + (size_t)B_DIM * T_DIM * D_DIM;   // then (B*S,T,D)

    dim3 grid(B_DIM * T_DIM / TPC);   // 2048 CTAs x 4 tokens
    dim3 block(512);
    ghc_kernel<<<grid, block>>>(resid, branch, rmsw, projW, log_sigma,
                                pre_logits, post_logits, out_bi, out_mix);
}